// round 2
// baseline (speedup 1.0000x reference)
#include <cuda_runtime.h>
#include <cuda_bf16.h>

#define BEV_H 512
#define BEV_W 512
#define BEV_C 64
#define HW (BEV_H * BEV_W)   // 262144 = 2^18
#define TILE 256             // cells per gather block

// Scratch: last-writer pillar index per BEV cell (up to 8 batches).
__device__ int g_last[8 * HW];
// Zero row for empty cells (zero-initialized, never written). 16B aligned for float4.
__device__ __align__(16) float g_zero[BEV_C];

// ---------------------------------------------------------------------------
// Scatter: last-occurrence-wins via atomicMax on pillar index.
// 4 pillars per thread, coords read as 3x int4 (48B, 16B-aligned stride).
// ---------------------------------------------------------------------------
__global__ void bev_scatter_kernel(const int* __restrict__ coords, int P) {
    int t = blockIdx.x * blockDim.x + threadIdx.x;
    int p0 = t * 4;
    if (p0 + 3 < P) {
        const int4* c4 = reinterpret_cast<const int4*>(coords + p0 * 3);
        int4 a = __ldg(c4 + 0);   // b0 r0 c0 b1
        int4 bb = __ldg(c4 + 1);  // r1 c1 b2 r2
        int4 cc = __ldg(c4 + 2);  // c2 b3 r3 c3
        int bs[4] = {a.x, a.w, bb.z, cc.y};
        int rs[4] = {a.y, bb.x, bb.w, cc.z};
        int cs[4] = {a.z, bb.y, cc.x, cc.w};
#pragma unroll
        for (int k = 0; k < 4; k++) {
            int r = min(max(rs[k], 0), BEV_H - 1);
            int c = min(max(cs[k], 0), BEV_W - 1);
            atomicMax(&g_last[bs[k] * HW + r * BEV_W + c], p0 + k);
        }
    } else {
        for (int p = p0; p < P; p++) {
            int b = coords[3 * p + 0];
            int r = min(max(coords[3 * p + 1], 0), BEV_H - 1);
            int c = min(max(coords[3 * p + 2], 0), BEV_W - 1);
            atomicMax(&g_last[b * HW + r * BEV_W + c], p);
        }
    }
}

// ---------------------------------------------------------------------------
// Gather + transpose. Block of 256 threads handles TILE=256 consecutive cells.
// Phase 1: 4 lanes cooperate per row (lane q loads float4 #q, q+4, q+8, q+12),
//          stage into 64KB smem with XOR swizzle (conflict-free STS.32).
// Phase 2: write out[b][ch][pos] as float4 along W (STG.128, fully coalesced;
//          LDS.128 conflict-free thanks to the swizzle).
// smem word layout: word(ch, cell) = ch*256 + (cell ^ (q(ch) << 3)),
// where q(ch) = (ch>>2)&3  (== the lane-quarter that produced that channel).
// ---------------------------------------------------------------------------
__global__ void __launch_bounds__(256) bev_gather_kernel(
    const float* __restrict__ feats,
    float* __restrict__ out) {
    extern __shared__ float smem[];  // 64 * 256 floats = 64KB

    const int tid = threadIdx.x;
    const int tile_base = blockIdx.x * TILE;         // global cell index of tile start
    const int b = tile_base >> 18;                   // tile never crosses a batch
    const int pos_base = tile_base & (HW - 1);

    const int q = tid & 3;           // lane quarter within the 4-lane row team
    const int cw = tid >> 2;         // 0..63: which cell within each group

    // ---- Phase 1: load rows, stage transposed into smem ----
#pragma unroll
    for (int g = 0; g < 4; g++) {
        const int cell_local = g * 64 + cw;                   // 0..255
        const int cell = tile_base + cell_local;
        const int last = __ldg(&g_last[cell]);
        const float4* row = reinterpret_cast<const float4*>(
            last >= 0 ? feats + (size_t)last * BEV_C : g_zero);

        float4 v0 = __ldg(row + q + 0);
        float4 v1 = __ldg(row + q + 4);
        float4 v2 = __ldg(row + q + 8);
        float4 v3 = __ldg(row + q + 12);

        const int csw = cell_local ^ (q << 3);                // swizzled cell index
        // channel of v_k = 4*(q + 4k) + j ; q(ch) == q for all of them.
        float* s0 = smem + (4 * (q + 0)) * 256 + csw;  // ch base 4q
        float* s1 = smem + (4 * (q + 4)) * 256 + csw;
        float* s2 = smem + (4 * (q + 8)) * 256 + csw;
        float* s3 = smem + (4 * (q + 12)) * 256 + csw;
        s0[0 * 256] = v0.x; s0[1 * 256] = v0.y; s0[2 * 256] = v0.z; s0[3 * 256] = v0.w;
        s1[0 * 256] = v1.x; s1[1 * 256] = v1.y; s1[2 * 256] = v1.z; s1[3 * 256] = v1.w;
        s2[0 * 256] = v2.x; s2[1 * 256] = v2.y; s2[2 * 256] = v2.z; s2[3 * 256] = v2.w;
        s3[0 * 256] = v3.x; s3[1 * 256] = v3.y; s3[2 * 256] = v3.z; s3[3 * 256] = v3.w;
    }

    __syncthreads();

    // ---- Phase 2: float4 stores along W ----
    float* out_b = out + (size_t)b * BEV_C * HW + pos_base;
#pragma unroll
    for (int it = 0; it < 16; it++) {
        const int idx = it * 256 + tid;     // 0..4095
        const int ch = idx >> 6;            // 0..63 (constant across a warp)
        const int quad = idx & 63;          // 0..63, warp-contiguous
        const int qq = (ch >> 2) & 3;
        const int quad_sw = quad ^ (qq << 1);
        float4 v = *reinterpret_cast<const float4*>(smem + ch * 256 + quad_sw * 4);
        *reinterpret_cast<float4*>(out_b + (size_t)ch * HW + quad * 4) = v;
    }
}

extern "C" void kernel_launch(void* const* d_in, const int* in_sizes, int n_in,
                              void* d_out, int out_size) {
    const float* feats  = (const float*)d_in[0];   // (P, 64) float32
    const int*   coords = (const int*)d_in[1];     // (P, 3) int32
    float*       out    = (float*)d_out;           // (B, 64, 512, 512) float32

    int P = in_sizes[0] / BEV_C;
    int B = out_size / (BEV_C * HW);
    if (B > 8) B = 8;
    int ncells = B * HW;

    // 1) init last-index grid to -1 via a graph memset node (0xFF bytes == -1 int)
    void* lastPtr = nullptr;
    cudaGetSymbolAddress(&lastPtr, g_last);
    cudaMemsetAsync(lastPtr, 0xFF, (size_t)ncells * sizeof(int), 0);

    // 2) scatter
    int nt = (P + 3) / 4;
    bev_scatter_kernel<<<(nt + 255) / 256, 256>>>(coords, P);

    // 3) gather + transpose (64KB dynamic smem -> opt in above 48KB default)
    static bool attr_set = false;
    if (!attr_set) {
        cudaFuncSetAttribute(bev_gather_kernel,
                             cudaFuncAttributeMaxDynamicSharedMemorySize,
                             64 * 1024);
        attr_set = true;
    }
    bev_gather_kernel<<<ncells / TILE, 256, 64 * 1024>>>(feats, out);
}

// round 3
// speedup vs baseline: 1.0763x; 1.0763x over previous
#include <cuda_runtime.h>
#include <cuda_bf16.h>

#define BEV_H 512
#define BEV_W 512
#define BEV_C 64
#define HW (BEV_H * BEV_W)   // 262144 = 2^18
#define TILE 128             // cells per gather block
#define GTHREADS 512

// Scratch: last-writer pillar index per BEV cell (up to 8 batches).
__device__ int g_last[8 * HW];
// Zero row for empty cells (zero-initialized, never written). 16B aligned.
__device__ __align__(16) float g_zero[BEV_C];

// ---------------------------------------------------------------------------
// Scatter: last-occurrence-wins via atomicMax on pillar index.
// ---------------------------------------------------------------------------
__global__ void bev_scatter_kernel(const int* __restrict__ coords, int P) {
    int t = blockIdx.x * blockDim.x + threadIdx.x;
    int p0 = t * 4;
    if (p0 + 3 < P) {
        const int4* c4 = reinterpret_cast<const int4*>(coords + p0 * 3);
        int4 a = __ldg(c4 + 0);   // b0 r0 c0 b1
        int4 bb = __ldg(c4 + 1);  // r1 c1 b2 r2
        int4 cc = __ldg(c4 + 2);  // c2 b3 r3 c3
        int bs[4] = {a.x, a.w, bb.z, cc.y};
        int rs[4] = {a.y, bb.x, bb.w, cc.z};
        int cs[4] = {a.z, bb.y, cc.x, cc.w};
#pragma unroll
        for (int k = 0; k < 4; k++) {
            int r = min(max(rs[k], 0), BEV_H - 1);
            int c = min(max(cs[k], 0), BEV_W - 1);
            atomicMax(&g_last[bs[k] * HW + r * BEV_W + c], p0 + k);
        }
    } else {
        for (int p = p0; p < P; p++) {
            int b = coords[3 * p + 0];
            int r = min(max(coords[3 * p + 1], 0), BEV_H - 1);
            int c = min(max(coords[3 * p + 2], 0), BEV_W - 1);
            atomicMax(&g_last[b * HW + r * BEV_W + c], p);
        }
    }
}

// ---------------------------------------------------------------------------
// Gather + transpose. 512 threads handle TILE=128 consecutive cells (32KB smem
// -> 4 CTAs/SM, 100% occupancy).
// Phase 1: 4-lane teams, one per cell: lane q loads float4 #q, q+4, q+8, q+12
//          of its row, stages into smem with XOR swizzle (conflict-free STS).
// Phase 2: out[b][ch][pos] written as float4 along W (coalesced STG.128,
//          conflict-free LDS.128 via the swizzle).
// smem word(ch, cell) = ch*TILE + (cell ^ (q(ch) << 3)),  q(ch) = (ch>>2)&3.
// ---------------------------------------------------------------------------
__global__ void __launch_bounds__(GTHREADS) bev_gather_kernel(
    const float* __restrict__ feats,
    float* __restrict__ out) {
    __shared__ float smem[BEV_C * TILE];  // 32KB

    const int tid = threadIdx.x;
    const int tile_base = blockIdx.x * TILE;   // tile never crosses a batch
    const int b = tile_base >> 18;
    const int pos_base = tile_base & (HW - 1);

    const int q  = tid & 3;     // lane quarter within the 4-lane row team
    const int cw = tid >> 2;    // 0..127: cell within tile

    // ---- Phase 1: gather rows, stage transposed into smem ----
    {
        const int last = __ldg(&g_last[tile_base + cw]);
        const float4* row = reinterpret_cast<const float4*>(
            last >= 0 ? feats + (size_t)last * BEV_C : g_zero);

        float4 v0 = __ldg(row + q + 0);
        float4 v1 = __ldg(row + q + 4);
        float4 v2 = __ldg(row + q + 8);
        float4 v3 = __ldg(row + q + 12);

        const int csw = cw ^ (q << 3);  // swizzled cell index
        float* s0 = smem + (4 * (q + 0))  * TILE + csw;
        float* s1 = smem + (4 * (q + 4))  * TILE + csw;
        float* s2 = smem + (4 * (q + 8))  * TILE + csw;
        float* s3 = smem + (4 * (q + 12)) * TILE + csw;
        s0[0 * TILE] = v0.x; s0[1 * TILE] = v0.y; s0[2 * TILE] = v0.z; s0[3 * TILE] = v0.w;
        s1[0 * TILE] = v1.x; s1[1 * TILE] = v1.y; s1[2 * TILE] = v1.z; s1[3 * TILE] = v1.w;
        s2[0 * TILE] = v2.x; s2[1 * TILE] = v2.y; s2[2 * TILE] = v2.z; s2[3 * TILE] = v2.w;
        s3[0 * TILE] = v3.x; s3[1 * TILE] = v3.y; s3[2 * TILE] = v3.z; s3[3 * TILE] = v3.w;
    }

    __syncthreads();

    // ---- Phase 2: float4 stores along W ----
    float* out_b = out + (size_t)b * BEV_C * HW + pos_base;
#pragma unroll
    for (int it = 0; it < (BEV_C * TILE / 4) / GTHREADS; it++) {  // 4 iters
        const int idx  = it * GTHREADS + tid;  // 0..2047 (quad index)
        const int ch   = idx >> 5;             // 0..63, constant across a warp
        const int quad = idx & 31;             // 0..31, warp-contiguous
        const int qq   = (ch >> 2) & 3;
        const int quad_sw = quad ^ (qq << 1);
        float4 v = *reinterpret_cast<const float4*>(smem + ch * TILE + quad_sw * 4);
        *reinterpret_cast<float4*>(out_b + (size_t)ch * HW + quad * 4) = v;
    }
}

extern "C" void kernel_launch(void* const* d_in, const int* in_sizes, int n_in,
                              void* d_out, int out_size) {
    const float* feats  = (const float*)d_in[0];   // (P, 64) float32
    const int*   coords = (const int*)d_in[1];     // (P, 3) int32
    float*       out    = (float*)d_out;           // (B, 64, 512, 512) float32

    int P = in_sizes[0] / BEV_C;
    int B = out_size / (BEV_C * HW);
    if (B > 8) B = 8;
    int ncells = B * HW;

    // 1) init last-index grid to -1 (memset node; 0xFF bytes == -1 int)
    void* lastPtr = nullptr;
    cudaGetSymbolAddress(&lastPtr, g_last);
    cudaMemsetAsync(lastPtr, 0xFF, (size_t)ncells * sizeof(int), 0);

    // 2) scatter
    int nt = (P + 3) / 4;
    bev_scatter_kernel<<<(nt + 255) / 256, 256>>>(coords, P);

    // 3) gather + transpose
    bev_gather_kernel<<<ncells / TILE, GTHREADS>>>(feats, out);
}